// round 1
// baseline (speedup 1.0000x reference)
#include <cuda_runtime.h>

// ---------------- scratch (device globals; no allocation allowed) ----------------
__device__ float g_y1[4*32*64*64];   // cv1 output
__device__ float g_y [4*64*64*64];   // cv2 output
__device__ float g_q [4*4096*8];     // q[b][n][8]
__device__ float g_k [4*4096*8];     // k[b][n][8]
__device__ float g_v [4*4096*64];    // v[b][n][64]
__device__ float g_ao[4*4096*64];    // attention out [b][n][64]

__device__ __forceinline__ float silu_f(float t) {
    return t * (1.0f / (1.0f + __expf(-t)));
}

// ---------------- conv3x3 + BN + SiLU ----------------
// Tile: 16 wide x 8 tall. Threads = 32 quads * (COUT/8).
// Each thread: 8 out-channels x 4 consecutive pixels.
template<int CIN, int COUT>
__global__ void conv_bn_silu_kernel(const float* __restrict__ xin,
                                    const float* __restrict__ w,
                                    const float* __restrict__ bg,
                                    const float* __restrict__ bb,
                                    const float* __restrict__ bm,
                                    const float* __restrict__ bv,
                                    float* __restrict__ out) {
    constexpr int CHUNK = 32;
    extern __shared__ __align__(16) float sm[];
    float* x_s = sm;                 // [CHUNK][10][20]
    float* w_s = sm + CHUNK*10*20;   // [CHUNK][9][COUT]

    const int b   = blockIdx.z;
    const int gy0 = blockIdx.y * 8;
    const int gx0 = blockIdx.x * 16;
    const int tid = threadIdx.x;
    const int quad = tid & 31;
    const int cog  = tid >> 5;
    const int py   = quad >> 2;
    const int px0  = (quad & 3) << 2;

    float acc[8][4];
#pragma unroll
    for (int i = 0; i < 8; i++)
#pragma unroll
        for (int j = 0; j < 4; j++) acc[i][j] = 0.f;

    for (int ch = 0; ch < CIN / CHUNK; ch++) {
        const float* xb = xin + (b*CIN + ch*CHUNK)*4096;
        for (int e = tid; e < CHUNK*10*18; e += blockDim.x) {
            int ci = e / 180; int rem = e % 180;
            int r = rem / 18; int c = rem % 18;
            int gy = gy0 - 1 + r, gx = gx0 - 1 + c;
            float val = 0.f;
            if ((unsigned)gy < 64u && (unsigned)gx < 64u)
                val = xb[ci*4096 + gy*64 + gx];
            x_s[(ci*10 + r)*20 + c] = val;
        }
        for (int e = tid; e < CHUNK*9*COUT; e += blockDim.x) {
            int co = e % COUT; int tap = (e / COUT) % 9; int ci = e / (COUT*9);
            w_s[(ci*9 + tap)*COUT + co] = w[(co*CIN + ch*CHUNK + ci)*9 + tap];
        }
        __syncthreads();

        for (int ci = 0; ci < CHUNK; ci++) {
            float xr[3][6];
#pragma unroll
            for (int d = 0; d < 3; d++)
#pragma unroll
                for (int k = 0; k < 6; k++)
                    xr[d][k] = x_s[(ci*10 + py + d)*20 + px0 + k];
            const float* wp = w_s + ci*9*COUT + cog*8;
#pragma unroll
            for (int co8 = 0; co8 < 8; co8++) {
#pragma unroll
                for (int tap = 0; tap < 9; tap++) {
                    float wv = wp[tap*COUT + co8];
                    int dy = tap / 3, dx = tap % 3;
#pragma unroll
                    for (int k = 0; k < 4; k++)
                        acc[co8][k] = fmaf(wv, xr[dy][dx + k], acc[co8][k]);
                }
            }
        }
        __syncthreads();
    }

#pragma unroll
    for (int co8 = 0; co8 < 8; co8++) {
        int co = cog*8 + co8;
        float scale = bg[co] * rsqrtf(bv[co] + 1e-5f);
        float shift = bb[co] - bm[co]*scale;
        float4 o;
        o.x = silu_f(acc[co8][0]*scale + shift);
        o.y = silu_f(acc[co8][1]*scale + shift);
        o.z = silu_f(acc[co8][2]*scale + shift);
        o.w = silu_f(acc[co8][3]*scale + shift);
        *reinterpret_cast<float4*>(out + (((b*COUT + co)*64 + gy0 + py)*64 + gx0 + px0)) = o;
    }
}

// ---------------- fused QKV projection ----------------
// Block: one batch, 256 tokens. Thread: one token, 80 outputs (8 q, 8 k, 64 v).
__global__ void qkv_kernel(const float* __restrict__ gy,
                           const float* __restrict__ q_w, const float* __restrict__ q_b,
                           const float* __restrict__ k_w, const float* __restrict__ k_b,
                           const float* __restrict__ v_w, const float* __restrict__ v_b,
                           float* __restrict__ gqo, float* __restrict__ gko,
                           float* __restrict__ gvo) {
    extern __shared__ __align__(16) float sm[];
    float* y_s = sm;            // [64][256]
    float* w_s = sm + 16384;    // [64][80] c-major
    float* b_s = sm + 21504;    // [80]
    const int b  = blockIdx.y;
    const int n0 = blockIdx.x * 256;
    const int tid = threadIdx.x;

    {
        const float* ybase = gy + (b*64)*4096 + n0;
        for (int f = tid; f < 4096; f += 256) {
            int c = f >> 6, i4 = f & 63;
            reinterpret_cast<float4*>(y_s + c*256)[i4] =
                reinterpret_cast<const float4*>(ybase + c*4096)[i4];
        }
    }
    for (int e = tid; e < 5120; e += 256) {
        int c = e / 80, o = e % 80;
        float val;
        if (o < 8)       val = q_w[o*64 + c];
        else if (o < 16) val = k_w[(o-8)*64 + c];
        else             val = v_w[(o-16)*64 + c];
        w_s[c*80 + o] = val;
    }
    if (tid < 80) {
        float val;
        if (tid < 8)       val = q_b[tid];
        else if (tid < 16) val = k_b[tid-8];
        else               val = v_b[tid-16];
        b_s[tid] = val;
    }
    __syncthreads();

    float acc[80];
#pragma unroll
    for (int o = 0; o < 80; o++) acc[o] = b_s[o];

    for (int c = 0; c < 64; c++) {
        float yv = y_s[c*256 + tid];
        const float4* wp = reinterpret_cast<const float4*>(w_s + c*80);
#pragma unroll
        for (int o4 = 0; o4 < 20; o4++) {
            float4 w4 = wp[o4];
            acc[o4*4+0] = fmaf(w4.x, yv, acc[o4*4+0]);
            acc[o4*4+1] = fmaf(w4.y, yv, acc[o4*4+1]);
            acc[o4*4+2] = fmaf(w4.z, yv, acc[o4*4+2]);
            acc[o4*4+3] = fmaf(w4.w, yv, acc[o4*4+3]);
        }
    }
    const int n = n0 + tid;
    float4* qd = reinterpret_cast<float4*>(gqo + (b*4096 + n)*8);
    qd[0] = make_float4(acc[0], acc[1], acc[2],  acc[3]);
    qd[1] = make_float4(acc[4], acc[5], acc[6],  acc[7]);
    float4* kd = reinterpret_cast<float4*>(gko + (b*4096 + n)*8);
    kd[0] = make_float4(acc[8], acc[9], acc[10], acc[11]);
    kd[1] = make_float4(acc[12],acc[13],acc[14], acc[15]);
    float4* vd = reinterpret_cast<float4*>(gvo + (b*4096 + n)*64);
#pragma unroll
    for (int o4 = 0; o4 < 16; o4++)
        vd[o4] = make_float4(acc[16+o4*4], acc[17+o4*4], acc[18+o4*4], acc[19+o4*4]);
}

// ---------------- flash attention (fp32, online softmax) ----------------
// BQ=128 queries/block, BK=64 keys/tile, 256 threads.
// Score role: thread pair per row (32 keys each). PV role: 4 rows x 8 channels.
__global__ void flash_kernel(const float* __restrict__ gq,
                             const float* __restrict__ gk,
                             const float* __restrict__ gv,
                             float* __restrict__ gao) {
    extern __shared__ __align__(16) float sm[];
    float* k_s   = sm;            // [64][8]   512
    float* v_s   = sm + 512;      // [64][64]  4096
    float* p_s   = sm + 4608;     // [128][65] 8320 (padded)
    float* f_s   = sm + 12928;    // [128]
    float* sum_s = sm + 13056;    // [128]

    const int b   = blockIdx.y;
    const int qt  = blockIdx.x;
    const int tid = threadIdx.x;
    const int si    = tid >> 1;
    const int shalf = tid & 1;
    const int rid   = tid >> 3;
    const int cg    = tid & 7;

    const float4* qrow = reinterpret_cast<const float4*>(gq + ((b*4096 + qt*128 + si) << 3));
    float4 q0 = qrow[0], q1 = qrow[1];

    float run_max = -1e30f, run_sum = 0.f;
    float acc[4][8];
#pragma unroll
    for (int r = 0; r < 4; r++)
#pragma unroll
        for (int c = 0; c < 8; c++) acc[r][c] = 0.f;

    const float* kb = gk + b*4096*8;
    const float* vb = gv + b*4096*64;

    for (int kt = 0; kt < 64; kt++) {
        if (tid < 128)
            reinterpret_cast<float4*>(k_s)[tid] =
                reinterpret_cast<const float4*>(kb + kt*512)[tid];
        {
            const float4* vsrc = reinterpret_cast<const float4*>(vb + kt*4096);
            float4* vdst = reinterpret_cast<float4*>(v_s);
#pragma unroll
            for (int t = 0; t < 4; t++)
                vdst[tid + t*256] = vsrc[tid + t*256];
        }
        __syncthreads();

        // ---- scores + online softmax ----
        float s[32];
        float tmax = -1e30f;
#pragma unroll
        for (int jj = 0; jj < 32; jj++) {
            int j = (shalf << 5) + jj;
            const float4* kp = reinterpret_cast<const float4*>(k_s + j*8);
            float4 k0 = kp[0], k1 = kp[1];
            float sv = q0.x*k0.x + q0.y*k0.y + q0.z*k0.z + q0.w*k0.w
                     + q1.x*k1.x + q1.y*k1.y + q1.z*k1.z + q1.w*k1.w;
            s[jj] = sv;
            tmax = fmaxf(tmax, sv);
        }
        tmax = fmaxf(tmax, __shfl_xor_sync(0xffffffffu, tmax, 1));
        float nmax = fmaxf(run_max, tmax);
        float f = __expf(run_max - nmax);
        float tsum = 0.f;
#pragma unroll
        for (int jj = 0; jj < 32; jj++) {
            float p = __expf(s[jj] - nmax);
            tsum += p;
            p_s[si*65 + (shalf << 5) + jj] = p;
        }
        tsum += __shfl_xor_sync(0xffffffffu, tsum, 1);
        run_sum = run_sum * f + tsum;
        run_max = nmax;
        if (shalf == 0) f_s[si] = f;
        __syncthreads();

        // ---- PV accumulation ----
        float fr0 = f_s[rid*4+0], fr1 = f_s[rid*4+1];
        float fr2 = f_s[rid*4+2], fr3 = f_s[rid*4+3];
#pragma unroll
        for (int c = 0; c < 8; c++) {
            acc[0][c] *= fr0; acc[1][c] *= fr1;
            acc[2][c] *= fr2; acc[3][c] *= fr3;
        }
#pragma unroll 8
        for (int j = 0; j < 64; j++) {
            const float4* vp = reinterpret_cast<const float4*>(v_s + j*64 + cg*8);
            float4 v0 = vp[0], v1 = vp[1];
#pragma unroll
            for (int r = 0; r < 4; r++) {
                float p = p_s[(rid*4 + r)*65 + j];
                acc[r][0] = fmaf(p, v0.x, acc[r][0]);
                acc[r][1] = fmaf(p, v0.y, acc[r][1]);
                acc[r][2] = fmaf(p, v0.z, acc[r][2]);
                acc[r][3] = fmaf(p, v0.w, acc[r][3]);
                acc[r][4] = fmaf(p, v1.x, acc[r][4]);
                acc[r][5] = fmaf(p, v1.y, acc[r][5]);
                acc[r][6] = fmaf(p, v1.z, acc[r][6]);
                acc[r][7] = fmaf(p, v1.w, acc[r][7]);
            }
        }
        __syncthreads();
    }

    if (shalf == 0) sum_s[si] = run_sum;
    __syncthreads();

    float* aob = gao + (b*4096 + qt*128)*64;
#pragma unroll
    for (int r = 0; r < 4; r++) {
        float inv = 1.0f / sum_s[rid*4 + r];
        float4 o0 = make_float4(acc[r][0]*inv, acc[r][1]*inv, acc[r][2]*inv, acc[r][3]*inv);
        float4 o1 = make_float4(acc[r][4]*inv, acc[r][5]*inv, acc[r][6]*inv, acc[r][7]*inv);
        float4* dst = reinterpret_cast<float4*>(aob + (rid*4 + r)*64 + cg*8);
        dst[0] = o0;
        dst[1] = o1;
    }
}

// ---------------- epilogue: out = x + 2*y + 2*gamma*ao (with [n][c]->[c][n] transpose) ----
__global__ void epilogue_kernel(const float* __restrict__ x,
                                const float* __restrict__ gy,
                                const float* __restrict__ gao,
                                const float* __restrict__ gamma,
                                float* __restrict__ out) {
    __shared__ float t_s[64][65];
    const int b  = blockIdx.y;
    const int n0 = blockIdx.x * 64;
    const int tid = threadIdx.x;

    const float4* src = reinterpret_cast<const float4*>(gao + (b*4096 + n0)*64);
#pragma unroll
    for (int t = 0; t < 4; t++) {
        int idx = tid + t*256;
        int row = idx >> 4, col4 = idx & 15;
        float4 v = src[idx];
        t_s[row][col4*4+0] = v.x;
        t_s[row][col4*4+1] = v.y;
        t_s[row][col4*4+2] = v.z;
        t_s[row][col4*4+3] = v.w;
    }
    __syncthreads();

    const float g2 = 2.0f * gamma[0];
    const int c  = tid >> 2;
    const int i0 = (tid & 3) * 16;
    const int base = (b*64 + c)*4096 + n0 + i0;
#pragma unroll
    for (int i4 = 0; i4 < 4; i4++) {
        float4 xv = reinterpret_cast<const float4*>(x  + base)[i4];
        float4 yv = reinterpret_cast<const float4*>(gy + base)[i4];
        float4 o;
        o.x = xv.x + 2.f*yv.x + g2*t_s[i0 + i4*4 + 0][c];
        o.y = xv.y + 2.f*yv.y + g2*t_s[i0 + i4*4 + 1][c];
        o.z = xv.z + 2.f*yv.z + g2*t_s[i0 + i4*4 + 2][c];
        o.w = xv.w + 2.f*yv.w + g2*t_s[i0 + i4*4 + 3][c];
        reinterpret_cast<float4*>(out + base)[i4] = o;
    }
}

// ---------------- launch ----------------
extern "C" void kernel_launch(void* const* d_in, const int* in_sizes, int n_in,
                              void* d_out, int out_size) {
    const float* x     = (const float*)d_in[0];
    const float* cv1_w = (const float*)d_in[1];
    const float* bn1_g = (const float*)d_in[2];
    const float* bn1_b = (const float*)d_in[3];
    const float* bn1_m = (const float*)d_in[4];
    const float* bn1_v = (const float*)d_in[5];
    const float* cv2_w = (const float*)d_in[6];
    const float* bn2_g = (const float*)d_in[7];
    const float* bn2_b = (const float*)d_in[8];
    const float* bn2_m = (const float*)d_in[9];
    const float* bn2_v = (const float*)d_in[10];
    const float* q_w   = (const float*)d_in[11];
    const float* q_b   = (const float*)d_in[12];
    const float* k_w   = (const float*)d_in[13];
    const float* k_b   = (const float*)d_in[14];
    const float* v_w   = (const float*)d_in[15];
    const float* v_b   = (const float*)d_in[16];
    const float* gamma = (const float*)d_in[17];
    float* out = (float*)d_out;

    void *py1, *py, *pq, *pk, *pv, *pao;
    cudaGetSymbolAddress(&py1, g_y1);
    cudaGetSymbolAddress(&py,  g_y);
    cudaGetSymbolAddress(&pq,  g_q);
    cudaGetSymbolAddress(&pk,  g_k);
    cudaGetSymbolAddress(&pv,  g_v);
    cudaGetSymbolAddress(&pao, g_ao);

    const int SMEM_C1 = (32*10*20 + 32*9*32) * 4;   // 62464
    const int SMEM_C2 = (32*10*20 + 32*9*64) * 4;   // 99328
    const int SMEM_QKV = (16384 + 5120 + 80) * 4;   // 86336
    const int SMEM_FA  = (512 + 4096 + 128*65 + 256) * 4;  // 52736

    cudaFuncSetAttribute(conv_bn_silu_kernel<64,32>, cudaFuncAttributeMaxDynamicSharedMemorySize, SMEM_C1);
    cudaFuncSetAttribute(conv_bn_silu_kernel<32,64>, cudaFuncAttributeMaxDynamicSharedMemorySize, SMEM_C2);
    cudaFuncSetAttribute(qkv_kernel,   cudaFuncAttributeMaxDynamicSharedMemorySize, SMEM_QKV);
    cudaFuncSetAttribute(flash_kernel, cudaFuncAttributeMaxDynamicSharedMemorySize, SMEM_FA);

    conv_bn_silu_kernel<64,32><<<dim3(4,8,4), 128, SMEM_C1>>>(
        x, cv1_w, bn1_g, bn1_b, bn1_m, bn1_v, (float*)py1);
    conv_bn_silu_kernel<32,64><<<dim3(4,8,4), 256, SMEM_C2>>>(
        (const float*)py1, cv2_w, bn2_g, bn2_b, bn2_m, bn2_v, (float*)py);
    qkv_kernel<<<dim3(16,4), 256, SMEM_QKV>>>(
        (const float*)py, q_w, q_b, k_w, k_b, v_w, v_b,
        (float*)pq, (float*)pk, (float*)pv);
    flash_kernel<<<dim3(32,4), 256, SMEM_FA>>>(
        (const float*)pq, (const float*)pk, (const float*)pv, (float*)pao);
    epilogue_kernel<<<dim3(64,4), 256>>>(
        x, (const float*)py, (const float*)pao, gamma, out);
}

// round 4
// speedup vs baseline: 3.2612x; 3.2612x over previous
#include <cuda_runtime.h>
#include <cstdint>

// ---------------- scratch (device globals; no allocation allowed) ----------------
__device__ float g_y1[4*32*64*64];   // cv1 output
__device__ float g_y [4*64*64*64];   // cv2 output
__device__ float g_q [4*4096*8];     // q[b][n][8]
__device__ float g_k [4*4096*8];     // k[b][n][8]
__device__ float g_v [4*4096*64];    // v[b][n][64]
__device__ float g_ao[4*4096*64];    // attention out [b][n][64]

__device__ __forceinline__ float silu_f(float t) {
    return t * (1.0f / (1.0f + __expf(-t)));
}
__device__ __forceinline__ uint32_t f2bf2(float lo, float hi) {
    uint32_t r;
    asm("cvt.rn.bf16x2.f32 %0, %1, %2;" : "=r"(r) : "f"(hi), "f"(lo));
    return r;
}
__device__ __forceinline__ uint32_t smem_u32(const void* p) {
    uint32_t a;
    asm("{ .reg .u64 t; cvta.to.shared.u64 t, %1; cvt.u32.u64 %0, t; }" : "=r"(a) : "l"(p));
    return a;
}

// ---------------- conv3x3 + BN + SiLU (unchanged from R1) ----------------
template<int CIN, int COUT>
__global__ void conv_bn_silu_kernel(const float* __restrict__ xin,
                                    const float* __restrict__ w,
                                    const float* __restrict__ bg,
                                    const float* __restrict__ bb,
                                    const float* __restrict__ bm,
                                    const float* __restrict__ bv,
                                    float* __restrict__ out) {
    constexpr int CHUNK = 32;
    extern __shared__ __align__(16) float sm[];
    float* x_s = sm;                 // [CHUNK][10][20]
    float* w_s = sm + CHUNK*10*20;   // [CHUNK][9][COUT]

    const int b   = blockIdx.z;
    const int gy0 = blockIdx.y * 8;
    const int gx0 = blockIdx.x * 16;
    const int tid = threadIdx.x;
    const int quad = tid & 31;
    const int cog  = tid >> 5;
    const int py   = quad >> 2;
    const int px0  = (quad & 3) << 2;

    float acc[8][4];
#pragma unroll
    for (int i = 0; i < 8; i++)
#pragma unroll
        for (int j = 0; j < 4; j++) acc[i][j] = 0.f;

    for (int ch = 0; ch < CIN / CHUNK; ch++) {
        const float* xb = xin + (b*CIN + ch*CHUNK)*4096;
        for (int e = tid; e < CHUNK*10*18; e += blockDim.x) {
            int ci = e / 180; int rem = e % 180;
            int r = rem / 18; int c = rem % 18;
            int gy = gy0 - 1 + r, gx = gx0 - 1 + c;
            float val = 0.f;
            if ((unsigned)gy < 64u && (unsigned)gx < 64u)
                val = xb[ci*4096 + gy*64 + gx];
            x_s[(ci*10 + r)*20 + c] = val;
        }
        for (int e = tid; e < CHUNK*9*COUT; e += blockDim.x) {
            int co = e % COUT; int tap = (e / COUT) % 9; int ci = e / (COUT*9);
            w_s[(ci*9 + tap)*COUT + co] = w[(co*CIN + ch*CHUNK + ci)*9 + tap];
        }
        __syncthreads();

        for (int ci = 0; ci < CHUNK; ci++) {
            float xr[3][6];
#pragma unroll
            for (int d = 0; d < 3; d++)
#pragma unroll
                for (int k = 0; k < 6; k++)
                    xr[d][k] = x_s[(ci*10 + py + d)*20 + px0 + k];
            const float* wp = w_s + ci*9*COUT + cog*8;
#pragma unroll
            for (int co8 = 0; co8 < 8; co8++) {
#pragma unroll
                for (int tap = 0; tap < 9; tap++) {
                    float wv = wp[tap*COUT + co8];
                    int dy = tap / 3, dx = tap % 3;
#pragma unroll
                    for (int k = 0; k < 4; k++)
                        acc[co8][k] = fmaf(wv, xr[dy][dx + k], acc[co8][k]);
                }
            }
        }
        __syncthreads();
    }

#pragma unroll
    for (int co8 = 0; co8 < 8; co8++) {
        int co = cog*8 + co8;
        float scale = bg[co] * rsqrtf(bv[co] + 1e-5f);
        float shift = bb[co] - bm[co]*scale;
        float4 o;
        o.x = silu_f(acc[co8][0]*scale + shift);
        o.y = silu_f(acc[co8][1]*scale + shift);
        o.z = silu_f(acc[co8][2]*scale + shift);
        o.w = silu_f(acc[co8][3]*scale + shift);
        *reinterpret_cast<float4*>(out + (((b*COUT + co)*64 + gy0 + py)*64 + gx0 + px0)) = o;
    }
}

// ---------------- fused QKV projection (unchanged from R1) ----------------
__global__ void qkv_kernel(const float* __restrict__ gy,
                           const float* __restrict__ q_w, const float* __restrict__ q_b,
                           const float* __restrict__ k_w, const float* __restrict__ k_b,
                           const float* __restrict__ v_w, const float* __restrict__ v_b,
                           float* __restrict__ gqo, float* __restrict__ gko,
                           float* __restrict__ gvo) {
    extern __shared__ __align__(16) float sm[];
    float* y_s = sm;            // [64][256]
    float* w_s = sm + 16384;    // [64][80] c-major
    float* b_s = sm + 21504;    // [80]
    const int b  = blockIdx.y;
    const int n0 = blockIdx.x * 256;
    const int tid = threadIdx.x;

    {
        const float* ybase = gy + (b*64)*4096 + n0;
        for (int f = tid; f < 4096; f += 256) {
            int c = f >> 6, i4 = f & 63;
            reinterpret_cast<float4*>(y_s + c*256)[i4] =
                reinterpret_cast<const float4*>(ybase + c*4096)[i4];
        }
    }
    for (int e = tid; e < 5120; e += 256) {
        int c = e / 80, o = e % 80;
        float val;
        if (o < 8)       val = q_w[o*64 + c];
        else if (o < 16) val = k_w[(o-8)*64 + c];
        else             val = v_w[(o-16)*64 + c];
        w_s[c*80 + o] = val;
    }
    if (tid < 80) {
        float val;
        if (tid < 8)       val = q_b[tid];
        else if (tid < 16) val = k_b[tid-8];
        else               val = v_b[tid-16];
        b_s[tid] = val;
    }
    __syncthreads();

    float acc[80];
#pragma unroll
    for (int o = 0; o < 80; o++) acc[o] = b_s[o];

    for (int c = 0; c < 64; c++) {
        float yv = y_s[c*256 + tid];
        const float4* wp = reinterpret_cast<const float4*>(w_s + c*80);
#pragma unroll
        for (int o4 = 0; o4 < 20; o4++) {
            float4 w4 = wp[o4];
            acc[o4*4+0] = fmaf(w4.x, yv, acc[o4*4+0]);
            acc[o4*4+1] = fmaf(w4.y, yv, acc[o4*4+1]);
            acc[o4*4+2] = fmaf(w4.z, yv, acc[o4*4+2]);
            acc[o4*4+3] = fmaf(w4.w, yv, acc[o4*4+3]);
        }
    }
    const int n = n0 + tid;
    float4* qd = reinterpret_cast<float4*>(gqo + (b*4096 + n)*8);
    qd[0] = make_float4(acc[0], acc[1], acc[2],  acc[3]);
    qd[1] = make_float4(acc[4], acc[5], acc[6],  acc[7]);
    float4* kd = reinterpret_cast<float4*>(gko + (b*4096 + n)*8);
    kd[0] = make_float4(acc[8], acc[9], acc[10], acc[11]);
    kd[1] = make_float4(acc[12],acc[13],acc[14], acc[15]);
    float4* vd = reinterpret_cast<float4*>(gvo + (b*4096 + n)*64);
#pragma unroll
    for (int o4 = 0; o4 < 16; o4++)
        vd[o4] = make_float4(acc[16+o4*4], acc[17+o4*4], acc[18+o4*4], acc[19+o4*4]);
}

// ---------------- flash attention via mma.sync (bf16 HMMA, online-max softmax) ----------------
// Grid (32,4), 256 threads = 8 warps. Warp w owns q-rows w*16..w*16+15 of the 128-row tile.
// QK: m16n8k8 (d=8 exact), B fragment via direct 32-bit LDS from K_s[key][8 bf16].
// PV: m16n8k16; B fragment via NON-trans ldmatrix.x4 from V^T smem (VT[ch][key], bf16),
//     which yields exactly B[k][n] (stored = B^T). No .trans semantics involved.
__global__ void __launch_bounds__(256, 1) flash_hmma_kernel(
        const float* __restrict__ gq,
        const float* __restrict__ gk,
        const float* __restrict__ gv,
        float* __restrict__ gao) {
    // K_s: 128 keys x 16B (8 bf16). VT_s: 64 ch rows x 272B (128 bf16 keys + 16B pad).
    __shared__ __align__(128) unsigned char K_s[2048];
    __shared__ __align__(128) unsigned char VT_s[64 * 272];
    const uint32_t VT_su = smem_u32(VT_s);

    const int b    = blockIdx.y;
    const int qt   = blockIdx.x;
    const int tid  = threadIdx.x;
    const int wid  = tid >> 5;
    const int lane = tid & 31;
    const int g    = lane >> 2;    // row-in-16 group (0..7)
    const int t    = lane & 3;     // col pair selector

    // ---- Q fragment (m16 k8 A operand), held all kernel ----
    const int qrow = b*4096 + qt*128 + wid*16 + g;
    float2 q0 = *reinterpret_cast<const float2*>(gq + (size_t)qrow*8 + 2*t);
    float2 q1 = *reinterpret_cast<const float2*>(gq + (size_t)(qrow+8)*8 + 2*t);
    const uint32_t qa0 = f2bf2(q0.x, q0.y);
    const uint32_t qa1 = f2bf2(q1.x, q1.y);

    float o[8][4];
#pragma unroll
    for (int i = 0; i < 8; i++)
#pragma unroll
        for (int j = 0; j < 4; j++) o[i][j] = 0.f;
    float rs0 = 0.f, rs1 = 0.f;          // running softmax sums (rows g, g+8)
    float m0 = -1e30f, m1 = -1e30f;      // running maxima

    const float* kb = gk + (size_t)b*4096*8;
    const float* vb = gv + (size_t)b*4096*64;

    // ldmatrix (non-trans) source address for PV B fragments:
    // matrix sel (lane>>3): 0 -> ch lo 8, key chunk lo; 1 -> ch lo, chunk hi;
    //                       2 -> ch hi 8, chunk lo;     3 -> ch hi, chunk hi.
    const int sel  = lane >> 3;
    const int l8   = lane & 7;
    const int ch_off   = ((sel >> 1) << 3) + l8;   // 0..15 within 16-ch group
    const int chunk_off = sel & 1;                  // 0/1 within kstep

    for (int kt = 0; kt < 32; kt++) {
        __syncthreads();   // previous tile fully consumed
        // ---- K tile -> smem bf16 [key][8] ----
        {
            int key = tid >> 1, h = tid & 1;
            float4 kv = *reinterpret_cast<const float4*>(kb + (size_t)(kt*128 + key)*8 + h*4);
            uint2 p = make_uint2(f2bf2(kv.x, kv.y), f2bf2(kv.z, kv.w));
            *reinterpret_cast<uint2*>(K_s + key*16 + h*8) = p;
        }
        // ---- V tile (128 tok x 64 ch) -> smem as V^T: VT[ch][key], bf16, chunk-xor swizzle ----
#pragma unroll
        for (int it = 0; it < 4; it++) {
            int id = it*256 + tid;        // 1024 tasks: keypair kp(64) x chgroup c4(16)
            int kp = id >> 4;             // key pair index (keys 2kp, 2kp+1)
            int c4 = id & 15;             // 4-channel group
            const float4* vr = reinterpret_cast<const float4*>(vb + (size_t)(kt*128 + 2*kp)*64) + c4;
            float4 va  = vr[0];
            float4 vb2 = vr[16];          // next token (+64 floats)
#pragma unroll
            for (int i = 0; i < 4; i++) {
                int ch = c4*4 + i;
                float lo = (i==0)?va.x :(i==1)?va.y :(i==2)?va.z :va.w;
                float hi = (i==0)?vb2.x:(i==1)?vb2.y:(i==2)?vb2.z:vb2.w;
                // byte = ch*272 + swizzled 16B chunk + word-in-chunk
                uint32_t byte = (uint32_t)(ch*272 + ((((kp>>2) ^ (ch>>3)) & 15) << 4) + (kp & 3)*4);
                *reinterpret_cast<uint32_t*>(VT_s + byte) = f2bf2(lo, hi);
            }
        }
        __syncthreads();

        // ---- QK: S[16 rows][128 keys] via 16x m16n8k8; B via direct LDS ----
        float e[16][4];
#pragma unroll
        for (int nt = 0; nt < 16; nt++) {
            uint32_t kb32 = *reinterpret_cast<const uint32_t*>(K_s + nt*128 + lane*4);
            float d0 = 0.f, d1 = 0.f, d2 = 0.f, d3 = 0.f;
            asm volatile(
                "mma.sync.aligned.m16n8k8.row.col.f32.bf16.bf16.f32 "
                "{%0,%1,%2,%3}, {%4,%5}, {%6}, {%0,%1,%2,%3};"
                : "+f"(d0), "+f"(d1), "+f"(d2), "+f"(d3)
                : "r"(qa0), "r"(qa1), "r"(kb32));
            e[nt][0] = d0; e[nt][1] = d1; e[nt][2] = d2; e[nt][3] = d3;
        }

        // ---- online-max softmax ----
        float tm0 = -1e30f, tm1 = -1e30f;
#pragma unroll
        for (int nt = 0; nt < 16; nt++) {
            tm0 = fmaxf(tm0, fmaxf(e[nt][0], e[nt][1]));
            tm1 = fmaxf(tm1, fmaxf(e[nt][2], e[nt][3]));
        }
        tm0 = fmaxf(tm0, __shfl_xor_sync(0xffffffffu, tm0, 1));
        tm0 = fmaxf(tm0, __shfl_xor_sync(0xffffffffu, tm0, 2));
        tm1 = fmaxf(tm1, __shfl_xor_sync(0xffffffffu, tm1, 1));
        tm1 = fmaxf(tm1, __shfl_xor_sync(0xffffffffu, tm1, 2));
        float m0n = fmaxf(m0, tm0), m1n = fmaxf(m1, tm1);
        float sc0 = __expf(m0 - m0n), sc1 = __expf(m1 - m1n);
        m0 = m0n; m1 = m1n;

        float ts0 = 0.f, ts1 = 0.f;
#pragma unroll
        for (int nt = 0; nt < 16; nt++) {
            e[nt][0] = __expf(e[nt][0] - m0n);
            e[nt][1] = __expf(e[nt][1] - m0n);
            e[nt][2] = __expf(e[nt][2] - m1n);
            e[nt][3] = __expf(e[nt][3] - m1n);
            ts0 += e[nt][0] + e[nt][1];
            ts1 += e[nt][2] + e[nt][3];
        }
        rs0 = rs0 * sc0 + ts0;
        rs1 = rs1 * sc1 + ts1;
#pragma unroll
        for (int nt = 0; nt < 8; nt++) {
            o[nt][0] *= sc0; o[nt][1] *= sc0;
            o[nt][2] *= sc1; o[nt][3] *= sc1;
        }

        // ---- PV: O += P x V, 8 ksteps of 16 keys; B via non-trans ldmatrix from VT ----
#pragma unroll
        for (int ks = 0; ks < 8; ks++) {
            uint32_t a0 = f2bf2(e[2*ks][0],   e[2*ks][1]);
            uint32_t a1 = f2bf2(e[2*ks][2],   e[2*ks][3]);
            uint32_t a2 = f2bf2(e[2*ks+1][0], e[2*ks+1][1]);
            uint32_t a3 = f2bf2(e[2*ks+1][2], e[2*ks+1][3]);
            int chunk = 2*ks + chunk_off;  // 16B chunk within VT row (= 8 keys)
#pragma unroll
            for (int nt2 = 0; nt2 < 4; nt2++) {
                int ch = nt2*16 + ch_off;
                uint32_t addr = VT_su +
                    (uint32_t)(ch*272 + (((chunk ^ (ch>>3)) & 15) << 4));
                uint32_t b0, b1, b2, b3;
                asm volatile(
                    "ldmatrix.sync.aligned.m8n8.x4.shared.b16 {%0,%1,%2,%3}, [%4];"
                    : "=r"(b0), "=r"(b1), "=r"(b2), "=r"(b3) : "r"(addr));
                asm volatile(
                    "mma.sync.aligned.m16n8k16.row.col.f32.bf16.bf16.f32 "
                    "{%0,%1,%2,%3}, {%4,%5,%6,%7}, {%8,%9}, {%0,%1,%2,%3};"
                    : "+f"(o[nt2*2][0]), "+f"(o[nt2*2][1]), "+f"(o[nt2*2][2]), "+f"(o[nt2*2][3])
                    : "r"(a0), "r"(a1), "r"(a2), "r"(a3), "r"(b0), "r"(b1));
                asm volatile(
                    "mma.sync.aligned.m16n8k16.row.col.f32.bf16.bf16.f32 "
                    "{%0,%1,%2,%3}, {%4,%5,%6,%7}, {%8,%9}, {%0,%1,%2,%3};"
                    : "+f"(o[nt2*2+1][0]), "+f"(o[nt2*2+1][1]), "+f"(o[nt2*2+1][2]), "+f"(o[nt2*2+1][3])
                    : "r"(a0), "r"(a1), "r"(a2), "r"(a3), "r"(b2), "r"(b3));
            }
        }
    }

    // ---- normalize + write ao[b][n][64] ----
    rs0 += __shfl_xor_sync(0xffffffffu, rs0, 1);
    rs0 += __shfl_xor_sync(0xffffffffu, rs0, 2);
    rs1 += __shfl_xor_sync(0xffffffffu, rs1, 1);
    rs1 += __shfl_xor_sync(0xffffffffu, rs1, 2);
    const float inv0 = 1.0f / rs0, inv1 = 1.0f / rs1;

    float* dst0 = gao + (size_t)qrow*64;
    float* dst1 = gao + (size_t)(qrow+8)*64;
#pragma unroll
    for (int nt = 0; nt < 8; nt++) {
        *reinterpret_cast<float2*>(dst0 + nt*8 + 2*t) =
            make_float2(o[nt][0]*inv0, o[nt][1]*inv0);
        *reinterpret_cast<float2*>(dst1 + nt*8 + 2*t) =
            make_float2(o[nt][2]*inv1, o[nt][3]*inv1);
    }
}

// ---------------- epilogue: out = x + 2*y + 2*gamma*ao ([n][c]->[c][n]) ----------------
__global__ void epilogue_kernel(const float* __restrict__ x,
                                const float* __restrict__ gy,
                                const float* __restrict__ gao,
                                const float* __restrict__ gamma,
                                float* __restrict__ out) {
    __shared__ float t_s[64][65];
    const int b  = blockIdx.y;
    const int n0 = blockIdx.x * 64;
    const int tid = threadIdx.x;

    const float4* src = reinterpret_cast<const float4*>(gao + (b*4096 + n0)*64);
#pragma unroll
    for (int t = 0; t < 4; t++) {
        int idx = tid + t*256;
        int row = idx >> 4, col4 = idx & 15;
        float4 v = src[idx];
        t_s[row][col4*4+0] = v.x;
        t_s[row][col4*4+1] = v.y;
        t_s[row][col4*4+2] = v.z;
        t_s[row][col4*4+3] = v.w;
    }
    __syncthreads();

    const float g2 = 2.0f * gamma[0];
    const int c  = tid >> 2;
    const int i0 = (tid & 3) * 16;
    const int base = (b*64 + c)*4096 + n0 + i0;
#pragma unroll
    for (int i4 = 0; i4 < 4; i4++) {
        float4 xv = reinterpret_cast<const float4*>(x  + base)[i4];
        float4 yv = reinterpret_cast<const float4*>(gy + base)[i4];
        float4 o;
        o.x = xv.x + 2.f*yv.x + g2*t_s[i0 + i4*4 + 0][c];
        o.y = xv.y + 2.f*yv.y + g2*t_s[i0 + i4*4 + 1][c];
        o.z = xv.z + 2.f*yv.z + g2*t_s[i0 + i4*4 + 2][c];
        o.w = xv.w + 2.f*yv.w + g2*t_s[i0 + i4*4 + 3][c];
        reinterpret_cast<float4*>(out + base)[i4] = o;
    }
}

// ---------------- launch ----------------
extern "C" void kernel_launch(void* const* d_in, const int* in_sizes, int n_in,
                              void* d_out, int out_size) {
    const float* x     = (const float*)d_in[0];
    const float* cv1_w = (const float*)d_in[1];
    const float* bn1_g = (const float*)d_in[2];
    const float* bn1_b = (const float*)d_in[3];
    const float* bn1_m = (const float*)d_in[4];
    const float* bn1_v = (const float*)d_in[5];
    const float* cv2_w = (const float*)d_in[6];
    const float* bn2_g = (const float*)d_in[7];
    const float* bn2_b = (const float*)d_in[8];
    const float* bn2_m = (const float*)d_in[9];
    const float* bn2_v = (const float*)d_in[10];
    const float* q_w   = (const float*)d_in[11];
    const float* q_b   = (const float*)d_in[12];
    const float* k_w   = (const float*)d_in[13];
    const float* k_b   = (const float*)d_in[14];
    const float* v_w   = (const float*)d_in[15];
    const float* v_b   = (const float*)d_in[16];
    const float* gamma = (const float*)d_in[17];
    float* out = (float*)d_out;

    void *py1, *py, *pq, *pk, *pv, *pao;
    cudaGetSymbolAddress(&py1, g_y1);
    cudaGetSymbolAddress(&py,  g_y);
    cudaGetSymbolAddress(&pq,  g_q);
    cudaGetSymbolAddress(&pk,  g_k);
    cudaGetSymbolAddress(&pv,  g_v);
    cudaGetSymbolAddress(&pao, g_ao);

    const int SMEM_C1  = (32*10*20 + 32*9*32) * 4;
    const int SMEM_C2  = (32*10*20 + 32*9*64) * 4;
    const int SMEM_QKV = (16384 + 5120 + 80) * 4;

    cudaFuncSetAttribute(conv_bn_silu_kernel<64,32>, cudaFuncAttributeMaxDynamicSharedMemorySize, SMEM_C1);
    cudaFuncSetAttribute(conv_bn_silu_kernel<32,64>, cudaFuncAttributeMaxDynamicSharedMemorySize, SMEM_C2);
    cudaFuncSetAttribute(qkv_kernel, cudaFuncAttributeMaxDynamicSharedMemorySize, SMEM_QKV);

    conv_bn_silu_kernel<64,32><<<dim3(4,8,4), 128, SMEM_C1>>>(
        x, cv1_w, bn1_g, bn1_b, bn1_m, bn1_v, (float*)py1);
    conv_bn_silu_kernel<32,64><<<dim3(4,8,4), 256, SMEM_C2>>>(
        (const float*)py1, cv2_w, bn2_g, bn2_b, bn2_m, bn2_v, (float*)py);
    qkv_kernel<<<dim3(16,4), 256, SMEM_QKV>>>(
        (const float*)py, q_w, q_b, k_w, k_b, v_w, v_b,
        (float*)pq, (float*)pk, (float*)pv);
    flash_hmma_kernel<<<dim3(32,4), 256>>>(
        (const float*)pq, (const float*)pk, (const float*)pv, (float*)pao);
    epilogue_kernel<<<dim3(64,4), 256>>>(
        x, (const float*)py, (const float*)pao, gamma, out);
}

// round 5
// speedup vs baseline: 3.8136x; 1.1694x over previous
#include <cuda_runtime.h>
#include <cstdint>

// ---------------- scratch (device globals; no allocation allowed) ----------------
__device__ float g_y1[4*32*64*64];   // cv1 output
__device__ float g_y [4*64*64*64];   // cv2 output
__device__ float g_q [4*4096*8];     // q[b][n][8]
__device__ float g_k [4*4096*8];     // k[b][n][8]
__device__ float g_v [4*4096*64];    // v[b][n][64]
__device__ float g_ao[4*4096*64];    // attention out [b][n][64]

__device__ __forceinline__ float silu_f(float t) {
    return t * (1.0f / (1.0f + __expf(-t)));
}
__device__ __forceinline__ uint32_t f2bf2(float lo, float hi) {
    uint32_t r;
    asm("cvt.rn.bf16x2.f32 %0, %1, %2;" : "=r"(r) : "f"(hi), "f"(lo));
    return r;
}
__device__ __forceinline__ uint32_t smem_u32(const void* p) {
    uint32_t a;
    asm("{ .reg .u64 t; cvta.to.shared.u64 t, %1; cvt.u32.u64 %0, t; }" : "=r"(a) : "l"(p));
    return a;
}

// ---------------- conv1: 3x3 + BN + SiLU (unchanged) ----------------
template<int CIN, int COUT>
__global__ void conv_bn_silu_kernel(const float* __restrict__ xin,
                                    const float* __restrict__ w,
                                    const float* __restrict__ bg,
                                    const float* __restrict__ bb,
                                    const float* __restrict__ bm,
                                    const float* __restrict__ bv,
                                    float* __restrict__ out) {
    constexpr int CHUNK = 32;
    extern __shared__ __align__(16) float sm[];
    float* x_s = sm;                 // [CHUNK][10][20]
    float* w_s = sm + CHUNK*10*20;   // [CHUNK][9][COUT]

    const int b   = blockIdx.z;
    const int gy0 = blockIdx.y * 8;
    const int gx0 = blockIdx.x * 16;
    const int tid = threadIdx.x;
    const int quad = tid & 31;
    const int cog  = tid >> 5;
    const int py   = quad >> 2;
    const int px0  = (quad & 3) << 2;

    float acc[8][4];
#pragma unroll
    for (int i = 0; i < 8; i++)
#pragma unroll
        for (int j = 0; j < 4; j++) acc[i][j] = 0.f;

    for (int ch = 0; ch < CIN / CHUNK; ch++) {
        const float* xb = xin + (b*CIN + ch*CHUNK)*4096;
        for (int e = tid; e < CHUNK*10*18; e += blockDim.x) {
            int ci = e / 180; int rem = e % 180;
            int r = rem / 18; int c = rem % 18;
            int gy = gy0 - 1 + r, gx = gx0 - 1 + c;
            float val = 0.f;
            if ((unsigned)gy < 64u && (unsigned)gx < 64u)
                val = xb[ci*4096 + gy*64 + gx];
            x_s[(ci*10 + r)*20 + c] = val;
        }
        for (int e = tid; e < CHUNK*9*COUT; e += blockDim.x) {
            int co = e % COUT; int tap = (e / COUT) % 9; int ci = e / (COUT*9);
            w_s[(ci*9 + tap)*COUT + co] = w[(co*CIN + ch*CHUNK + ci)*9 + tap];
        }
        __syncthreads();

        for (int ci = 0; ci < CHUNK; ci++) {
            float xr[3][6];
#pragma unroll
            for (int d = 0; d < 3; d++)
#pragma unroll
                for (int k = 0; k < 6; k++)
                    xr[d][k] = x_s[(ci*10 + py + d)*20 + px0 + k];
            const float* wp = w_s + ci*9*COUT + cog*8;
#pragma unroll
            for (int co8 = 0; co8 < 8; co8++) {
#pragma unroll
                for (int tap = 0; tap < 9; tap++) {
                    float wv = wp[tap*COUT + co8];
                    int dy = tap / 3, dx = tap % 3;
#pragma unroll
                    for (int k = 0; k < 4; k++)
                        acc[co8][k] = fmaf(wv, xr[dy][dx + k], acc[co8][k]);
                }
            }
        }
        __syncthreads();
    }

#pragma unroll
    for (int co8 = 0; co8 < 8; co8++) {
        int co = cog*8 + co8;
        float scale = bg[co] * rsqrtf(bv[co] + 1e-5f);
        float shift = bb[co] - bm[co]*scale;
        float4 o;
        o.x = silu_f(acc[co8][0]*scale + shift);
        o.y = silu_f(acc[co8][1]*scale + shift);
        o.z = silu_f(acc[co8][2]*scale + shift);
        o.w = silu_f(acc[co8][3]*scale + shift);
        *reinterpret_cast<float4*>(out + (((b*COUT + co)*64 + gy0 + py)*64 + gx0 + px0)) = o;
    }
}

// ---------------- conv2 (3x3+BN+SiLU) with FUSED QKV projection ----------------
// Same conv structure (CIN=32, COUT=64, 256 threads). After the conv epilogue the
// 128-pixel x 64-channel y tile is staged in smem and q/k/v are computed in-block
// (2 threads per pixel, 40 outputs each), eliminating the separate qkv kernel.
__global__ void conv2_qkv_kernel(const float* __restrict__ xin,
                                 const float* __restrict__ w,
                                 const float* __restrict__ bg,
                                 const float* __restrict__ bb,
                                 const float* __restrict__ bm,
                                 const float* __restrict__ bv,
                                 const float* __restrict__ q_w, const float* __restrict__ q_b,
                                 const float* __restrict__ k_w, const float* __restrict__ k_b,
                                 const float* __restrict__ v_w, const float* __restrict__ v_b,
                                 float* __restrict__ out,
                                 float* __restrict__ gqo, float* __restrict__ gko,
                                 float* __restrict__ gvo) {
    constexpr int CIN = 32, COUT = 64, CHUNK = 32;
    extern __shared__ __align__(16) float sm[];
    float* x_s = sm;                 // [32][10][20]
    float* w_s = sm + CHUNK*10*20;   // [32][9][64]
    // phase-2 overlay (after conv loop):
    float* y_t  = sm;                // [128][65]
    float* wq_s = sm + 8320;         // [64][80] c-major
    float* qb_s = sm + 8320 + 5120;  // [80]

    const int b   = blockIdx.z;
    const int gy0 = blockIdx.y * 8;
    const int gx0 = blockIdx.x * 16;
    const int tid = threadIdx.x;
    const int quad = tid & 31;
    const int cog  = tid >> 5;
    const int py   = quad >> 2;
    const int px0  = (quad & 3) << 2;

    float acc[8][4];
#pragma unroll
    for (int i = 0; i < 8; i++)
#pragma unroll
        for (int j = 0; j < 4; j++) acc[i][j] = 0.f;

    for (int ch = 0; ch < CIN / CHUNK; ch++) {
        const float* xb = xin + (b*CIN + ch*CHUNK)*4096;
        for (int e = tid; e < CHUNK*10*18; e += blockDim.x) {
            int ci = e / 180; int rem = e % 180;
            int r = rem / 18; int c = rem % 18;
            int gy = gy0 - 1 + r, gx = gx0 - 1 + c;
            float val = 0.f;
            if ((unsigned)gy < 64u && (unsigned)gx < 64u)
                val = xb[ci*4096 + gy*64 + gx];
            x_s[(ci*10 + r)*20 + c] = val;
        }
        for (int e = tid; e < CHUNK*9*COUT; e += blockDim.x) {
            int co = e % COUT; int tap = (e / COUT) % 9; int ci = e / (COUT*9);
            w_s[(ci*9 + tap)*COUT + co] = w[(co*CIN + ch*CHUNK + ci)*9 + tap];
        }
        __syncthreads();

        for (int ci = 0; ci < CHUNK; ci++) {
            float xr[3][6];
#pragma unroll
            for (int d = 0; d < 3; d++)
#pragma unroll
                for (int k = 0; k < 6; k++)
                    xr[d][k] = x_s[(ci*10 + py + d)*20 + px0 + k];
            const float* wp = w_s + ci*9*COUT + cog*8;
#pragma unroll
            for (int co8 = 0; co8 < 8; co8++) {
#pragma unroll
                for (int tap = 0; tap < 9; tap++) {
                    float wv = wp[tap*COUT + co8];
                    int dy = tap / 3, dx = tap % 3;
#pragma unroll
                    for (int k = 0; k < 4; k++)
                        acc[co8][k] = fmaf(wv, xr[dy][dx + k], acc[co8][k]);
                }
            }
        }
        __syncthreads();
    }

    // ---- conv epilogue: BN+SiLU -> gmem y AND smem y_t ----
    const int pbase = py*16 + px0;
#pragma unroll
    for (int co8 = 0; co8 < 8; co8++) {
        int co = cog*8 + co8;
        float scale = bg[co] * rsqrtf(bv[co] + 1e-5f);
        float shift = bb[co] - bm[co]*scale;
        float4 o;
        o.x = silu_f(acc[co8][0]*scale + shift);
        o.y = silu_f(acc[co8][1]*scale + shift);
        o.z = silu_f(acc[co8][2]*scale + shift);
        o.w = silu_f(acc[co8][3]*scale + shift);
        *reinterpret_cast<float4*>(out + (((b*COUT + co)*64 + gy0 + py)*64 + gx0 + px0)) = o;
        y_t[(pbase+0)*65 + co] = o.x;
        y_t[(pbase+1)*65 + co] = o.y;
        y_t[(pbase+2)*65 + co] = o.z;
        y_t[(pbase+3)*65 + co] = o.w;
    }
    // ---- load qkv weights (c-major [64][80]) + biases ----
    for (int e = tid; e < 5120; e += 256) {
        int c = e / 80, o = e % 80;
        float val;
        if (o < 8)       val = q_w[o*64 + c];
        else if (o < 16) val = k_w[(o-8)*64 + c];
        else             val = v_w[(o-16)*64 + c];
        wq_s[c*80 + o] = val;
    }
    if (tid < 80) {
        float val;
        if (tid < 8)       val = q_b[tid];
        else if (tid < 16) val = k_b[tid-8];
        else               val = v_b[tid-16];
        qb_s[tid] = val;
    }
    __syncthreads();

    // ---- qkv: 2 threads per pixel, 40 outputs each ----
    const int px   = tid >> 1;
    const int half = tid & 1;
    float a2[40];
    const float* bb2 = qb_s + half*40;
#pragma unroll
    for (int j = 0; j < 40; j++) a2[j] = bb2[j];
    for (int c = 0; c < 64; c++) {
        float yv = y_t[px*65 + c];
        const float4* wp = reinterpret_cast<const float4*>(wq_s + c*80 + half*40);
#pragma unroll
        for (int j4 = 0; j4 < 10; j4++) {
            float4 w4 = wp[j4];
            a2[j4*4+0] = fmaf(w4.x, yv, a2[j4*4+0]);
            a2[j4*4+1] = fmaf(w4.y, yv, a2[j4*4+1]);
            a2[j4*4+2] = fmaf(w4.z, yv, a2[j4*4+2]);
            a2[j4*4+3] = fmaf(w4.w, yv, a2[j4*4+3]);
        }
    }
    const int n = (gy0 + (px >> 4))*64 + gx0 + (px & 15);
    if (half == 0) {
        float4* qd = reinterpret_cast<float4*>(gqo + (size_t)(b*4096 + n)*8);
        qd[0] = make_float4(a2[0], a2[1], a2[2],  a2[3]);
        qd[1] = make_float4(a2[4], a2[5], a2[6],  a2[7]);
        float4* kd = reinterpret_cast<float4*>(gko + (size_t)(b*4096 + n)*8);
        kd[0] = make_float4(a2[8],  a2[9],  a2[10], a2[11]);
        kd[1] = make_float4(a2[12], a2[13], a2[14], a2[15]);
        float4* vd = reinterpret_cast<float4*>(gvo + (size_t)(b*4096 + n)*64);
#pragma unroll
        for (int j = 0; j < 6; j++)
            vd[j] = make_float4(a2[16+4*j], a2[17+4*j], a2[18+4*j], a2[19+4*j]);
    } else {
        float4* vd = reinterpret_cast<float4*>(gvo + (size_t)(b*4096 + n)*64 + 24);
#pragma unroll
        for (int j = 0; j < 10; j++)
            vd[j] = make_float4(a2[4*j], a2[1+4*j], a2[2+4*j], a2[3+4*j]);
    }
}

// ---------------- flash attention (bf16 HMMA, no-max softmax, double-buffered) ---------
// Grid (32,4), 256 threads = 8 warps. Warp w owns q-rows w*16..+15 of the 128-row tile.
// QK: m16n8k8 (d=8 exact). PV: m16n8k16, B via non-trans ldmatrix.x4 from VT smem.
// Scores are small (|s| <~ 40 worst case << 88): exp without max cannot overflow;
// O accumulates monotonically in registers; single normalize at the end.
__device__ __forceinline__ void ld_ktile(const float* kb, int kt, int tid, float4& kv) {
    int key = tid >> 1, h = tid & 1;
    kv = *reinterpret_cast<const float4*>(kb + (size_t)(kt*128 + key)*8 + h*4);
}
__device__ __forceinline__ void st_ktile(unsigned char* K_s, int tid, const float4& kv) {
    int key = tid >> 1, h = tid & 1;
    *reinterpret_cast<uint2*>(K_s + key*16 + h*8) =
        make_uint2(f2bf2(kv.x, kv.y), f2bf2(kv.z, kv.w));
}
__device__ __forceinline__ void ld_vtile(const float* vb, int kt, int tid,
                                         float4* va, float4* vb2) {
#pragma unroll
    for (int it = 0; it < 4; it++) {
        int id = it*256 + tid;
        int kp = id >> 4, c4 = id & 15;
        const float4* vr = reinterpret_cast<const float4*>(vb + (size_t)(kt*128 + 2*kp)*64) + c4;
        va[it]  = vr[0];
        vb2[it] = vr[16];
    }
}
__device__ __forceinline__ void st_vtile(unsigned char* VT_s, int tid,
                                         const float4* va, const float4* vb2) {
#pragma unroll
    for (int it = 0; it < 4; it++) {
        int id = it*256 + tid;
        int kp = id >> 4, c4 = id & 15;
#pragma unroll
        for (int i = 0; i < 4; i++) {
            int ch = c4*4 + i;
            float lo = (i==0)?va[it].x :(i==1)?va[it].y :(i==2)?va[it].z :va[it].w;
            float hi = (i==0)?vb2[it].x:(i==1)?vb2[it].y:(i==2)?vb2[it].z:vb2[it].w;
            uint32_t byte = (uint32_t)(ch*272 + ((((kp>>2) ^ (ch>>3)) & 15) << 4) + (kp & 3)*4);
            *reinterpret_cast<uint32_t*>(VT_s + byte) = f2bf2(lo, hi);
        }
    }
}

__global__ void __launch_bounds__(256, 1) flash_hmma_kernel(
        const float* __restrict__ gq,
        const float* __restrict__ gk,
        const float* __restrict__ gv,
        float* __restrict__ gao) {
    __shared__ __align__(128) unsigned char K_s[2][2048];
    __shared__ __align__(128) unsigned char VT_s[2][64 * 272];
    const uint32_t VT_su0 = smem_u32(VT_s[0]);
    const uint32_t VT_su1 = smem_u32(VT_s[1]);

    const int b    = blockIdx.y;
    const int qt   = blockIdx.x;
    const int tid  = threadIdx.x;
    const int wid  = tid >> 5;
    const int lane = tid & 31;
    const int g    = lane >> 2;
    const int t    = lane & 3;

    const int qrow = b*4096 + qt*128 + wid*16 + g;
    float2 q0 = *reinterpret_cast<const float2*>(gq + (size_t)qrow*8 + 2*t);
    float2 q1 = *reinterpret_cast<const float2*>(gq + (size_t)(qrow+8)*8 + 2*t);
    const uint32_t qa0 = f2bf2(q0.x, q0.y);
    const uint32_t qa1 = f2bf2(q1.x, q1.y);

    float o[8][4];
#pragma unroll
    for (int i = 0; i < 8; i++)
#pragma unroll
        for (int j = 0; j < 4; j++) o[i][j] = 0.f;
    float rs0 = 0.f, rs1 = 0.f;

    const float* kb = gk + (size_t)b*4096*8;
    const float* vb = gv + (size_t)b*4096*64;

    const int sel  = lane >> 3;
    const int l8   = lane & 7;
    const int ch_off    = ((sel >> 1) << 3) + l8;
    const int chunk_off = sel & 1;

    // prologue: tile 0 -> buffer 0
    float4 kv_pf; float4 va_pf[4], vb_pf[4];
    ld_ktile(kb, 0, tid, kv_pf);
    ld_vtile(vb, 0, tid, va_pf, vb_pf);
    st_ktile(K_s[0], tid, kv_pf);
    st_vtile(VT_s[0], tid, va_pf, vb_pf);
    __syncthreads();

    for (int kt = 0; kt < 32; kt++) {
        const int cur = kt & 1, nxt = cur ^ 1;
        const uint32_t vbase = cur ? VT_su1 : VT_su0;

        // prefetch next tile (LDG latency hidden under QK/exp)
        if (kt < 31) {
            ld_ktile(kb, kt+1, tid, kv_pf);
            ld_vtile(vb, kt+1, tid, va_pf, vb_pf);
        }

        // ---- QK: S[16 rows][128 keys] via 16x m16n8k8 ----
        float e[16][4];
#pragma unroll
        for (int nt = 0; nt < 16; nt++) {
            uint32_t kb32 = *reinterpret_cast<const uint32_t*>(K_s[cur] + nt*128 + lane*4);
            float d0 = 0.f, d1 = 0.f, d2 = 0.f, d3 = 0.f;
            asm volatile(
                "mma.sync.aligned.m16n8k8.row.col.f32.bf16.bf16.f32 "
                "{%0,%1,%2,%3}, {%4,%5}, {%6}, {%0,%1,%2,%3};"
                : "+f"(d0), "+f"(d1), "+f"(d2), "+f"(d3)
                : "r"(qa0), "r"(qa1), "r"(kb32));
            e[nt][0] = d0; e[nt][1] = d1; e[nt][2] = d2; e[nt][3] = d3;
        }
        // ---- exp (no max) + row sums ----
#pragma unroll
        for (int nt = 0; nt < 16; nt++) {
            e[nt][0] = __expf(e[nt][0]);
            e[nt][1] = __expf(e[nt][1]);
            e[nt][2] = __expf(e[nt][2]);
            e[nt][3] = __expf(e[nt][3]);
            rs0 += e[nt][0] + e[nt][1];
            rs1 += e[nt][2] + e[nt][3];
        }

        // stage next tile into the other buffer (prev reads of it finished last iter)
        if (kt < 31) {
            st_ktile(K_s[nxt], tid, kv_pf);
            st_vtile(VT_s[nxt], tid, va_pf, vb_pf);
        }

        // ---- PV: O += P x V ----
#pragma unroll
        for (int ks = 0; ks < 8; ks++) {
            uint32_t a0 = f2bf2(e[2*ks][0],   e[2*ks][1]);
            uint32_t a1 = f2bf2(e[2*ks][2],   e[2*ks][3]);
            uint32_t a2 = f2bf2(e[2*ks+1][0], e[2*ks+1][1]);
            uint32_t a3 = f2bf2(e[2*ks+1][2], e[2*ks+1][3]);
            int chunk = 2*ks + chunk_off;
#pragma unroll
            for (int nt2 = 0; nt2 < 4; nt2++) {
                int ch = nt2*16 + ch_off;
                uint32_t addr = vbase + (uint32_t)(ch*272 + (((chunk ^ (ch>>3)) & 15) << 4));
                uint32_t b0, b1, b2, b3;
                asm volatile(
                    "ldmatrix.sync.aligned.m8n8.x4.shared.b16 {%0,%1,%2,%3}, [%4];"
                    : "=r"(b0), "=r"(b1), "=r"(b2), "=r"(b3) : "r"(addr));
                asm volatile(
                    "mma.sync.aligned.m16n8k16.row.col.f32.bf16.bf16.f32 "
                    "{%0,%1,%2,%3}, {%4,%5,%6,%7}, {%8,%9}, {%0,%1,%2,%3};"
                    : "+f"(o[nt2*2][0]), "+f"(o[nt2*2][1]), "+f"(o[nt2*2][2]), "+f"(o[nt2*2][3])
                    : "r"(a0), "r"(a1), "r"(a2), "r"(a3), "r"(b0), "r"(b1));
                asm volatile(
                    "mma.sync.aligned.m16n8k16.row.col.f32.bf16.bf16.f32 "
                    "{%0,%1,%2,%3}, {%4,%5,%6,%7}, {%8,%9}, {%0,%1,%2,%3};"
                    : "+f"(o[nt2*2+1][0]), "+f"(o[nt2*2+1][1]), "+f"(o[nt2*2+1][2]), "+f"(o[nt2*2+1][3])
                    : "r"(a0), "r"(a1), "r"(a2), "r"(a3), "r"(b2), "r"(b3));
            }
        }
        __syncthreads();
    }

    // ---- normalize + write ao[b][n][64] ----
    rs0 += __shfl_xor_sync(0xffffffffu, rs0, 1);
    rs0 += __shfl_xor_sync(0xffffffffu, rs0, 2);
    rs1 += __shfl_xor_sync(0xffffffffu, rs1, 1);
    rs1 += __shfl_xor_sync(0xffffffffu, rs1, 2);
    const float inv0 = 1.0f / rs0, inv1 = 1.0f / rs1;

    float* dst0 = gao + (size_t)qrow*64;
    float* dst1 = gao + (size_t)(qrow+8)*64;
#pragma unroll
    for (int nt = 0; nt < 8; nt++) {
        *reinterpret_cast<float2*>(dst0 + nt*8 + 2*t) =
            make_float2(o[nt][0]*inv0, o[nt][1]*inv0);
        *reinterpret_cast<float2*>(dst1 + nt*8 + 2*t) =
            make_float2(o[nt][2]*inv1, o[nt][3]*inv1);
    }
}

// ---------------- epilogue: out = x + 2*y + 2*gamma*ao ([n][c]->[c][n]) ----------------
__global__ void epilogue_kernel(const float* __restrict__ x,
                                const float* __restrict__ gy,
                                const float* __restrict__ gao,
                                const float* __restrict__ gamma,
                                float* __restrict__ out) {
    __shared__ float t_s[64][65];
    const int b  = blockIdx.y;
    const int n0 = blockIdx.x * 64;
    const int tid = threadIdx.x;

    const float4* src = reinterpret_cast<const float4*>(gao + (b*4096 + n0)*64);
#pragma unroll
    for (int t = 0; t < 4; t++) {
        int idx = tid + t*256;
        int row = idx >> 4, col4 = idx & 15;
        float4 v = src[idx];
        t_s[row][col4*4+0] = v.x;
        t_s[row][col4*4+1] = v.y;
        t_s[row][col4*4+2] = v.z;
        t_s[row][col4*4+3] = v.w;
    }
    __syncthreads();

    const float g2 = 2.0f * gamma[0];
    const int c  = tid >> 2;
    const int i0 = (tid & 3) * 16;
    const int base = (b*64 + c)*4096 + n0 + i0;
#pragma unroll
    for (int i4 = 0; i4 < 4; i4++) {
        float4 xv = reinterpret_cast<const float4*>(x  + base)[i4];
        float4 yv = reinterpret_cast<const float4*>(gy + base)[i4];
        float4 o;
        o.x = xv.x + 2.f*yv.x + g2*t_s[i0 + i4*4 + 0][c];
        o.y = xv.y + 2.f*yv.y + g2*t_s[i0 + i4*4 + 1][c];
        o.z = xv.z + 2.f*yv.z + g2*t_s[i0 + i4*4 + 2][c];
        o.w = xv.w + 2.f*yv.w + g2*t_s[i0 + i4*4 + 3][c];
        reinterpret_cast<float4*>(out + base)[i4] = o;
    }
}

// ---------------- launch ----------------
extern "C" void kernel_launch(void* const* d_in, const int* in_sizes, int n_in,
                              void* d_out, int out_size) {
    const float* x     = (const float*)d_in[0];
    const float* cv1_w = (const float*)d_in[1];
    const float* bn1_g = (const float*)d_in[2];
    const float* bn1_b = (const float*)d_in[3];
    const float* bn1_m = (const float*)d_in[4];
    const float* bn1_v = (const float*)d_in[5];
    const float* cv2_w = (const float*)d_in[6];
    const float* bn2_g = (const float*)d_in[7];
    const float* bn2_b = (const float*)d_in[8];
    const float* bn2_m = (const float*)d_in[9];
    const float* bn2_v = (const float*)d_in[10];
    const float* q_w   = (const float*)d_in[11];
    const float* q_b   = (const float*)d_in[12];
    const float* k_w   = (const float*)d_in[13];
    const float* k_b   = (const float*)d_in[14];
    const float* v_w   = (const float*)d_in[15];
    const float* v_b   = (const float*)d_in[16];
    const float* gamma = (const float*)d_in[17];
    float* out = (float*)d_out;

    void *py1, *py, *pq, *pk, *pv, *pao;
    cudaGetSymbolAddress(&py1, g_y1);
    cudaGetSymbolAddress(&py,  g_y);
    cudaGetSymbolAddress(&pq,  g_q);
    cudaGetSymbolAddress(&pk,  g_k);
    cudaGetSymbolAddress(&pv,  g_v);
    cudaGetSymbolAddress(&pao, g_ao);

    const int SMEM_C1 = (32*10*20 + 32*9*32) * 4;   // 62464
    const int SMEM_C2 = (32*10*20 + 32*9*64) * 4;   // 99328 (phase-2 overlay fits within)

    cudaFuncSetAttribute(conv_bn_silu_kernel<64,32>, cudaFuncAttributeMaxDynamicSharedMemorySize, SMEM_C1);
    cudaFuncSetAttribute(conv2_qkv_kernel, cudaFuncAttributeMaxDynamicSharedMemorySize, SMEM_C2);

    conv_bn_silu_kernel<64,32><<<dim3(4,8,4), 128, SMEM_C1>>>(
        x, cv1_w, bn1_g, bn1_b, bn1_m, bn1_v, (float*)py1);
    conv2_qkv_kernel<<<dim3(4,8,4), 256, SMEM_C2>>>(
        (const float*)py1, cv2_w, bn2_g, bn2_b, bn2_m, bn2_v,
        q_w, q_b, k_w, k_b, v_w, v_b,
        (float*)py, (float*)pq, (float*)pk, (float*)pv);
    flash_hmma_kernel<<<dim3(32,4), 256>>>(
        (const float*)pq, (const float*)pk, (const float*)pv, (float*)pao);
    epilogue_kernel<<<dim3(64,4), 256>>>(
        x, (const float*)py, (const float*)pao, gamma, out);
}

// round 6
// speedup vs baseline: 3.8550x; 1.0108x over previous
#include <cuda_runtime.h>
#include <cstdint>

// ---------------- scratch (device globals; no allocation allowed) ----------------
__device__ float g_y1[4*32*64*64];   // cv1 output
__device__ float g_y [4*64*64*64];   // cv2 output
__device__ float g_q [4*4096*8];     // q[b][n][8]
__device__ float g_k [4*4096*8];     // k[b][n][8]
__device__ float g_v [4*4096*64];    // v[b][n][64]

__device__ __forceinline__ float silu_f(float t) {
    return t * (1.0f / (1.0f + __expf(-t)));
}
__device__ __forceinline__ uint32_t f2bf2(float lo, float hi) {
    uint32_t r;
    asm("cvt.rn.bf16x2.f32 %0, %1, %2;" : "=r"(r) : "f"(hi), "f"(lo));
    return r;
}
__device__ __forceinline__ uint32_t smem_u32(const void* p) {
    uint32_t a;
    asm("{ .reg .u64 t; cvta.to.shared.u64 t, %1; cvt.u32.u64 %0, t; }" : "=r"(a) : "l"(p));
    return a;
}

// ---------------- conv1: 3x3 + BN + SiLU (256 threads, 4co x 4px/thread) ----------------
__global__ void conv1_kernel(const float* __restrict__ xin,
                             const float* __restrict__ w,
                             const float* __restrict__ bg,
                             const float* __restrict__ bb,
                             const float* __restrict__ bm,
                             const float* __restrict__ bv,
                             float* __restrict__ out) {
    constexpr int CIN = 64, COUT = 32, CHUNK = 32;
    extern __shared__ __align__(16) float sm[];
    float* x_s = sm;                 // [32][10][20]
    float* w_s = sm + CHUNK*10*20;   // [32][9][32]

    const int b   = blockIdx.z;
    const int gy0 = blockIdx.y * 8;
    const int gx0 = blockIdx.x * 16;
    const int tid = threadIdx.x;
    const int quad = tid & 31;
    const int cog  = tid >> 5;          // 0..7 -> 4 channels each
    const int py   = quad >> 2;
    const int px0  = (quad & 3) << 2;

    float acc[4][4];
#pragma unroll
    for (int i = 0; i < 4; i++)
#pragma unroll
        for (int j = 0; j < 4; j++) acc[i][j] = 0.f;

    for (int ch = 0; ch < CIN / CHUNK; ch++) {
        const float* xb = xin + (b*CIN + ch*CHUNK)*4096;
        for (int e = tid; e < CHUNK*10*18; e += 256) {
            int ci = e / 180; int rem = e % 180;
            int r = rem / 18; int c = rem % 18;
            int gy = gy0 - 1 + r, gx = gx0 - 1 + c;
            float val = 0.f;
            if ((unsigned)gy < 64u && (unsigned)gx < 64u)
                val = xb[ci*4096 + gy*64 + gx];
            x_s[(ci*10 + r)*20 + c] = val;
        }
        for (int e = tid; e < CHUNK*9*COUT; e += 256) {
            int co = e % COUT; int tap = (e / COUT) % 9; int ci = e / (COUT*9);
            w_s[(ci*9 + tap)*COUT + co] = w[(co*CIN + ch*CHUNK + ci)*9 + tap];
        }
        __syncthreads();

        for (int ci = 0; ci < CHUNK; ci++) {
            float xr[3][6];
#pragma unroll
            for (int d = 0; d < 3; d++)
#pragma unroll
                for (int k = 0; k < 6; k++)
                    xr[d][k] = x_s[(ci*10 + py + d)*20 + px0 + k];
            const float* wp = w_s + ci*9*COUT + cog*4;
#pragma unroll
            for (int c4 = 0; c4 < 4; c4++) {
#pragma unroll
                for (int tap = 0; tap < 9; tap++) {
                    float wv = wp[tap*COUT + c4];
                    int dy = tap / 3, dx = tap % 3;
#pragma unroll
                    for (int k = 0; k < 4; k++)
                        acc[c4][k] = fmaf(wv, xr[dy][dx + k], acc[c4][k]);
                }
            }
        }
        __syncthreads();
    }

#pragma unroll
    for (int c4 = 0; c4 < 4; c4++) {
        int co = cog*4 + c4;
        float scale = bg[co] * rsqrtf(bv[co] + 1e-5f);
        float shift = bb[co] - bm[co]*scale;
        float4 o;
        o.x = silu_f(acc[c4][0]*scale + shift);
        o.y = silu_f(acc[c4][1]*scale + shift);
        o.z = silu_f(acc[c4][2]*scale + shift);
        o.w = silu_f(acc[c4][3]*scale + shift);
        *reinterpret_cast<float4*>(out + (((b*COUT + co)*64 + gy0 + py)*64 + gx0 + px0)) = o;
    }
}

// ---------------- conv2 (3x3+BN+SiLU) + fused QKV (512 threads) ----------------
__global__ void conv2_qkv_kernel(const float* __restrict__ xin,
                                 const float* __restrict__ w,
                                 const float* __restrict__ bg,
                                 const float* __restrict__ bb,
                                 const float* __restrict__ bm,
                                 const float* __restrict__ bv,
                                 const float* __restrict__ q_w, const float* __restrict__ q_b,
                                 const float* __restrict__ k_w, const float* __restrict__ k_b,
                                 const float* __restrict__ v_w, const float* __restrict__ v_b,
                                 float* __restrict__ out,
                                 float* __restrict__ gqo, float* __restrict__ gko,
                                 float* __restrict__ gvo) {
    constexpr int CIN = 32, COUT = 64, CHUNK = 32;
    extern __shared__ __align__(16) float sm[];
    float* x_s = sm;                 // [32][10][20]
    float* w_s = sm + CHUNK*10*20;   // [32][9][64]
    // phase-2 overlay:
    float* y_t  = sm;                // [128][65]
    float* wq_s = sm + 8320;         // [64][80]
    float* qb_s = sm + 8320 + 5120;  // [80]

    const int b   = blockIdx.z;
    const int gy0 = blockIdx.y * 8;
    const int gx0 = blockIdx.x * 16;
    const int tid = threadIdx.x;
    const int quad = tid & 31;
    const int cog  = tid >> 5;          // 0..15 -> 4 channels each
    const int py   = quad >> 2;
    const int px0  = (quad & 3) << 2;

    float acc[4][4];
#pragma unroll
    for (int i = 0; i < 4; i++)
#pragma unroll
        for (int j = 0; j < 4; j++) acc[i][j] = 0.f;

    {
        const float* xb = xin + (b*CIN)*4096;
        for (int e = tid; e < CHUNK*10*18; e += 512) {
            int ci = e / 180; int rem = e % 180;
            int r = rem / 18; int c = rem % 18;
            int gy = gy0 - 1 + r, gx = gx0 - 1 + c;
            float val = 0.f;
            if ((unsigned)gy < 64u && (unsigned)gx < 64u)
                val = xb[ci*4096 + gy*64 + gx];
            x_s[(ci*10 + r)*20 + c] = val;
        }
        for (int e = tid; e < CHUNK*9*COUT; e += 512) {
            int co = e % COUT; int tap = (e / COUT) % 9; int ci = e / (COUT*9);
            w_s[(ci*9 + tap)*COUT + co] = w[(co*CIN + ci)*9 + tap];
        }
        __syncthreads();

        for (int ci = 0; ci < CHUNK; ci++) {
            float xr[3][6];
#pragma unroll
            for (int d = 0; d < 3; d++)
#pragma unroll
                for (int k = 0; k < 6; k++)
                    xr[d][k] = x_s[(ci*10 + py + d)*20 + px0 + k];
            const float* wp = w_s + ci*9*COUT + cog*4;
#pragma unroll
            for (int c4 = 0; c4 < 4; c4++) {
#pragma unroll
                for (int tap = 0; tap < 9; tap++) {
                    float wv = wp[tap*COUT + c4];
                    int dy = tap / 3, dx = tap % 3;
#pragma unroll
                    for (int k = 0; k < 4; k++)
                        acc[c4][k] = fmaf(wv, xr[dy][dx + k], acc[c4][k]);
                }
            }
        }
        __syncthreads();
    }

    // ---- conv epilogue: BN+SiLU -> gmem y AND smem y_t ----
    const int pbase = py*16 + px0;
#pragma unroll
    for (int c4 = 0; c4 < 4; c4++) {
        int co = cog*4 + c4;
        float scale = bg[co] * rsqrtf(bv[co] + 1e-5f);
        float shift = bb[co] - bm[co]*scale;
        float4 o;
        o.x = silu_f(acc[c4][0]*scale + shift);
        o.y = silu_f(acc[c4][1]*scale + shift);
        o.z = silu_f(acc[c4][2]*scale + shift);
        o.w = silu_f(acc[c4][3]*scale + shift);
        *reinterpret_cast<float4*>(out + (((b*COUT + co)*64 + gy0 + py)*64 + gx0 + px0)) = o;
        y_t[(pbase+0)*65 + co] = o.x;
        y_t[(pbase+1)*65 + co] = o.y;
        y_t[(pbase+2)*65 + co] = o.z;
        y_t[(pbase+3)*65 + co] = o.w;
    }
    // ---- qkv weights ([64][80] c-major) + biases ----
    for (int e = tid; e < 5120; e += 512) {
        int c = e / 80, o = e % 80;
        float val;
        if (o < 8)       val = q_w[o*64 + c];
        else if (o < 16) val = k_w[(o-8)*64 + c];
        else             val = v_w[(o-16)*64 + c];
        wq_s[c*80 + o] = val;
    }
    if (tid < 80) {
        float val;
        if (tid < 8)       val = q_b[tid];
        else if (tid < 16) val = k_b[tid-8];
        else               val = v_b[tid-16];
        qb_s[tid] = val;
    }
    __syncthreads();

    // ---- qkv: 4 threads per pixel, 20 outputs each ----
    const int px  = tid >> 2;
    const int qtr = tid & 3;
    float a2[20];
    const float* bb2 = qb_s + qtr*20;
#pragma unroll
    for (int j = 0; j < 20; j++) a2[j] = bb2[j];
    for (int c = 0; c < 64; c++) {
        float yv = y_t[px*65 + c];
        const float4* wp = reinterpret_cast<const float4*>(wq_s + c*80 + qtr*20);
#pragma unroll
        for (int j4 = 0; j4 < 5; j4++) {
            float4 w4 = wp[j4];
            a2[j4*4+0] = fmaf(w4.x, yv, a2[j4*4+0]);
            a2[j4*4+1] = fmaf(w4.y, yv, a2[j4*4+1]);
            a2[j4*4+2] = fmaf(w4.z, yv, a2[j4*4+2]);
            a2[j4*4+3] = fmaf(w4.w, yv, a2[j4*4+3]);
        }
    }
    const int n = (gy0 + (px >> 4))*64 + gx0 + (px & 15);
    if (qtr == 0) {
        float4* qd = reinterpret_cast<float4*>(gqo + (size_t)(b*4096 + n)*8);
        qd[0] = make_float4(a2[0], a2[1], a2[2],  a2[3]);
        qd[1] = make_float4(a2[4], a2[5], a2[6],  a2[7]);
        float4* kd = reinterpret_cast<float4*>(gko + (size_t)(b*4096 + n)*8);
        kd[0] = make_float4(a2[8],  a2[9],  a2[10], a2[11]);
        kd[1] = make_float4(a2[12], a2[13], a2[14], a2[15]);
        *reinterpret_cast<float4*>(gvo + (size_t)(b*4096 + n)*64) =
            make_float4(a2[16], a2[17], a2[18], a2[19]);
    } else {
        float* vd = gvo + (size_t)(b*4096 + n)*64 + (qtr*20 - 16);
#pragma unroll
        for (int j = 0; j < 5; j++)
            *reinterpret_cast<float4*>(vd + 4*j) =
                make_float4(a2[4*j], a2[1+4*j], a2[2+4*j], a2[3+4*j]);
    }
}

// ---------------- flash attention + fused output epilogue ----------------
// Grid (32,4), 256 threads = 8 warps. Warp w owns q-rows w*16..+15 of the 128-row tile.
// QK: m16n8k8 (d=8 exact). PV: m16n8k16, B via non-trans ldmatrix.x4 from VT smem.
// No-max softmax (scores small, fp32 exp safe); O accumulates in registers.
// Final: out[b][c][n] = x + 2y + 2*gamma*attn written directly via smem transpose.
__device__ __forceinline__ void ld_ktile(const float* kb, int kt, int tid, float4& kv) {
    int key = tid >> 1, h = tid & 1;
    kv = *reinterpret_cast<const float4*>(kb + (size_t)(kt*128 + key)*8 + h*4);
}
__device__ __forceinline__ void st_ktile(unsigned char* K_s, int tid, const float4& kv) {
    int key = tid >> 1, h = tid & 1;
    *reinterpret_cast<uint2*>(K_s + key*16 + h*8) =
        make_uint2(f2bf2(kv.x, kv.y), f2bf2(kv.z, kv.w));
}
__device__ __forceinline__ void ld_vtile(const float* vb, int kt, int tid,
                                         float4* va, float4* vb2) {
#pragma unroll
    for (int it = 0; it < 4; it++) {
        int id = it*256 + tid;
        int kp = id >> 4, c4 = id & 15;
        const float4* vr = reinterpret_cast<const float4*>(vb + (size_t)(kt*128 + 2*kp)*64) + c4;
        va[it]  = vr[0];
        vb2[it] = vr[16];
    }
}
__device__ __forceinline__ void st_vtile(unsigned char* VT_s, int tid,
                                         const float4* va, const float4* vb2) {
#pragma unroll
    for (int it = 0; it < 4; it++) {
        int id = it*256 + tid;
        int kp = id >> 4, c4 = id & 15;
#pragma unroll
        for (int i = 0; i < 4; i++) {
            int ch = c4*4 + i;
            float lo = (i==0)?va[it].x :(i==1)?va[it].y :(i==2)?va[it].z :va[it].w;
            float hi = (i==0)?vb2[it].x:(i==1)?vb2[it].y:(i==2)?vb2[it].z:vb2[it].w;
            uint32_t byte = (uint32_t)(ch*272 + ((((kp>>2) ^ (ch>>3)) & 15) << 4) + (kp & 3)*4);
            *reinterpret_cast<uint32_t*>(VT_s + byte) = f2bf2(lo, hi);
        }
    }
}

__global__ void __launch_bounds__(256, 1) flash_hmma_kernel(
        const float* __restrict__ gq,
        const float* __restrict__ gk,
        const float* __restrict__ gv,
        const float* __restrict__ x,
        const float* __restrict__ gy,
        const float* __restrict__ gamma,
        float* __restrict__ outp) {
    __shared__ __align__(128) unsigned char smem_all[2*2048 + 2*17408];  // 38912B
    unsigned char* K_s0  = smem_all;
    unsigned char* K_s1  = smem_all + 2048;
    unsigned char* VT_s0 = smem_all + 4096;
    unsigned char* VT_s1 = smem_all + 4096 + 17408;
    const uint32_t VT_su0 = smem_u32(VT_s0);
    const uint32_t VT_su1 = smem_u32(VT_s1);
    float* t_s = reinterpret_cast<float*>(smem_all);   // overlay [128][66] = 33792B

    const int b    = blockIdx.y;
    const int qt   = blockIdx.x;
    const int tid  = threadIdx.x;
    const int wid  = tid >> 5;
    const int lane = tid & 31;
    const int g    = lane >> 2;
    const int t    = lane & 3;

    const int qrow = b*4096 + qt*128 + wid*16 + g;
    float2 q0 = *reinterpret_cast<const float2*>(gq + (size_t)qrow*8 + 2*t);
    float2 q1 = *reinterpret_cast<const float2*>(gq + (size_t)(qrow+8)*8 + 2*t);
    const uint32_t qa0 = f2bf2(q0.x, q0.y);
    const uint32_t qa1 = f2bf2(q1.x, q1.y);

    float o[8][4];
#pragma unroll
    for (int i = 0; i < 8; i++)
#pragma unroll
        for (int j = 0; j < 4; j++) o[i][j] = 0.f;
    float rs0 = 0.f, rs1 = 0.f;

    const float* kb = gk + (size_t)b*4096*8;
    const float* vb = gv + (size_t)b*4096*64;

    const int sel  = lane >> 3;
    const int l8   = lane & 7;
    const int ch_off    = ((sel >> 1) << 3) + l8;
    const int chunk_off = sel & 1;

    float4 kv_pf; float4 va_pf[4], vb_pf[4];
    ld_ktile(kb, 0, tid, kv_pf);
    ld_vtile(vb, 0, tid, va_pf, vb_pf);
    st_ktile(K_s0, tid, kv_pf);
    st_vtile(VT_s0, tid, va_pf, vb_pf);
    __syncthreads();

    for (int kt = 0; kt < 32; kt++) {
        const int cur = kt & 1;
        const uint32_t vbase = cur ? VT_su1 : VT_su0;
        unsigned char* Kc = cur ? K_s1 : K_s0;

        if (kt < 31) {
            ld_ktile(kb, kt+1, tid, kv_pf);
            ld_vtile(vb, kt+1, tid, va_pf, vb_pf);
        }

        // ---- QK ----
        float e[16][4];
#pragma unroll
        for (int nt = 0; nt < 16; nt++) {
            uint32_t kb32 = *reinterpret_cast<const uint32_t*>(Kc + nt*128 + lane*4);
            float d0 = 0.f, d1 = 0.f, d2 = 0.f, d3 = 0.f;
            asm volatile(
                "mma.sync.aligned.m16n8k8.row.col.f32.bf16.bf16.f32 "
                "{%0,%1,%2,%3}, {%4,%5}, {%6}, {%0,%1,%2,%3};"
                : "+f"(d0), "+f"(d1), "+f"(d2), "+f"(d3)
                : "r"(qa0), "r"(qa1), "r"(kb32));
            e[nt][0] = d0; e[nt][1] = d1; e[nt][2] = d2; e[nt][3] = d3;
        }
#pragma unroll
        for (int nt = 0; nt < 16; nt++) {
            e[nt][0] = __expf(e[nt][0]);
            e[nt][1] = __expf(e[nt][1]);
            e[nt][2] = __expf(e[nt][2]);
            e[nt][3] = __expf(e[nt][3]);
            rs0 += e[nt][0] + e[nt][1];
            rs1 += e[nt][2] + e[nt][3];
        }

        if (kt < 31) {
            st_ktile(cur ? K_s0 : K_s1, tid, kv_pf);
            st_vtile(cur ? VT_s0 : VT_s1, tid, va_pf, vb_pf);
        }

        // ---- PV ----
#pragma unroll
        for (int ks = 0; ks < 8; ks++) {
            uint32_t a0 = f2bf2(e[2*ks][0],   e[2*ks][1]);
            uint32_t a1 = f2bf2(e[2*ks][2],   e[2*ks][3]);
            uint32_t a2 = f2bf2(e[2*ks+1][0], e[2*ks+1][1]);
            uint32_t a3 = f2bf2(e[2*ks+1][2], e[2*ks+1][3]);
            int chunk = 2*ks + chunk_off;
#pragma unroll
            for (int nt2 = 0; nt2 < 4; nt2++) {
                int ch = nt2*16 + ch_off;
                uint32_t addr = vbase + (uint32_t)(ch*272 + (((chunk ^ (ch>>3)) & 15) << 4));
                uint32_t b0, b1, b2, b3;
                asm volatile(
                    "ldmatrix.sync.aligned.m8n8.x4.shared.b16 {%0,%1,%2,%3}, [%4];"
                    : "=r"(b0), "=r"(b1), "=r"(b2), "=r"(b3) : "r"(addr));
                asm volatile(
                    "mma.sync.aligned.m16n8k16.row.col.f32.bf16.bf16.f32 "
                    "{%0,%1,%2,%3}, {%4,%5,%6,%7}, {%8,%9}, {%0,%1,%2,%3};"
                    : "+f"(o[nt2*2][0]), "+f"(o[nt2*2][1]), "+f"(o[nt2*2][2]), "+f"(o[nt2*2][3])
                    : "r"(a0), "r"(a1), "r"(a2), "r"(a3), "r"(b0), "r"(b1));
                asm volatile(
                    "mma.sync.aligned.m16n8k16.row.col.f32.bf16.bf16.f32 "
                    "{%0,%1,%2,%3}, {%4,%5,%6,%7}, {%8,%9}, {%0,%1,%2,%3};"
                    : "+f"(o[nt2*2+1][0]), "+f"(o[nt2*2+1][1]), "+f"(o[nt2*2+1][2]), "+f"(o[nt2*2+1][3])
                    : "r"(a0), "r"(a1), "r"(a2), "r"(a3), "r"(b2), "r"(b3));
            }
        }
        __syncthreads();
    }

    // ---- normalize, transpose via smem, write out = x + 2y + 2*gamma*attn ----
    rs0 += __shfl_xor_sync(0xffffffffu, rs0, 1);
    rs0 += __shfl_xor_sync(0xffffffffu, rs0, 2);
    rs1 += __shfl_xor_sync(0xffffffffu, rs1, 1);
    rs1 += __shfl_xor_sync(0xffffffffu, rs1, 2);
    const float inv0 = 1.0f / rs0, inv1 = 1.0f / rs1;

    const int r0 = wid*16 + g;        // local row (0..127)
#pragma unroll
    for (int nt = 0; nt < 8; nt++) {
        int ch = nt*8 + 2*t;
        *reinterpret_cast<float2*>(t_s + r0*66 + ch) =
            make_float2(o[nt][0]*inv0, o[nt][1]*inv0);
        *reinterpret_cast<float2*>(t_s + (r0+8)*66 + ch) =
            make_float2(o[nt][2]*inv1, o[nt][3]*inv1);
    }
    __syncthreads();

    const float g2 = 2.0f * gamma[0];
    const int c  = tid >> 2;           // 0..63
    const int i0 = (tid & 3) * 32;     // 0,32,64,96
    const size_t base = ((size_t)(b*64 + c))*4096 + qt*128 + i0;
#pragma unroll
    for (int i4 = 0; i4 < 8; i4++) {
        float4 xv = *reinterpret_cast<const float4*>(x  + base + i4*4);
        float4 yv = *reinterpret_cast<const float4*>(gy + base + i4*4);
        float4 ov;
        ov.x = xv.x + 2.f*yv.x + g2*t_s[(i0 + i4*4 + 0)*66 + c];
        ov.y = xv.y + 2.f*yv.y + g2*t_s[(i0 + i4*4 + 1)*66 + c];
        ov.z = xv.z + 2.f*yv.z + g2*t_s[(i0 + i4*4 + 2)*66 + c];
        ov.w = xv.w + 2.f*yv.w + g2*t_s[(i0 + i4*4 + 3)*66 + c];
        *reinterpret_cast<float4*>(outp + base + i4*4) = ov;
    }
}

// ---------------- launch ----------------
extern "C" void kernel_launch(void* const* d_in, const int* in_sizes, int n_in,
                              void* d_out, int out_size) {
    const float* x     = (const float*)d_in[0];
    const float* cv1_w = (const float*)d_in[1];
    const float* bn1_g = (const float*)d_in[2];
    const float* bn1_b = (const float*)d_in[3];
    const float* bn1_m = (const float*)d_in[4];
    const float* bn1_v = (const float*)d_in[5];
    const float* cv2_w = (const float*)d_in[6];
    const float* bn2_g = (const float*)d_in[7];
    const float* bn2_b = (const float*)d_in[8];
    const float* bn2_m = (const float*)d_in[9];
    const float* bn2_v = (const float*)d_in[10];
    const float* q_w   = (const float*)d_in[11];
    const float* q_b   = (const float*)d_in[12];
    const float* k_w   = (const float*)d_in[13];
    const float* k_b   = (const float*)d_in[14];
    const float* v_w   = (const float*)d_in[15];
    const float* v_b   = (const float*)d_in[16];
    const float* gamma = (const float*)d_in[17];
    float* out = (float*)d_out;

    void *py1, *py, *pq, *pk, *pv;
    cudaGetSymbolAddress(&py1, g_y1);
    cudaGetSymbolAddress(&py,  g_y);
    cudaGetSymbolAddress(&pq,  g_q);
    cudaGetSymbolAddress(&pk,  g_k);
    cudaGetSymbolAddress(&pv,  g_v);

    const int SMEM_C1 = (32*10*20 + 32*9*32) * 4;   // 62464
    const int SMEM_C2 = (32*10*20 + 32*9*64) * 4;   // 99328

    cudaFuncSetAttribute(conv1_kernel, cudaFuncAttributeMaxDynamicSharedMemorySize, SMEM_C1);
    cudaFuncSetAttribute(conv2_qkv_kernel, cudaFuncAttributeMaxDynamicSharedMemorySize, SMEM_C2);

    conv1_kernel<<<dim3(4,8,4), 256, SMEM_C1>>>(
        x, cv1_w, bn1_g, bn1_b, bn1_m, bn1_v, (float*)py1);
    conv2_qkv_kernel<<<dim3(4,8,4), 512, SMEM_C2>>>(
        (const float*)py1, cv2_w, bn2_g, bn2_b, bn2_m, bn2_v,
        q_w, q_b, k_w, k_b, v_w, v_b,
        (float*)py, (float*)pq, (float*)pk, (float*)pv);
    flash_hmma_kernel<<<dim3(32,4), 256>>>(
        (const float*)pq, (const float*)pk, (const float*)pv,
        x, (const float*)py, gamma, out);
}